// round 5
// baseline (speedup 1.0000x reference)
#include <cuda_runtime.h>
#include <cuda_bf16.h>
#include <cstdint>

#define N_NODES 100000
#define N_EDGES 1250000
#define D       64
#define NBLK    391           // ceil(N_NODES/256)

// Scratch (no allocs allowed)
__device__ float    g_agg[(size_t)N_NODES * D];
__device__ int      g_deg[N_NODES];
__device__ int      g_off[N_NODES];
__device__ int      g_cursor[N_NODES];
__device__ int      g_eidx[N_EDGES];
__device__ float    g_norm[N_NODES];
// bits[0:30)=value, bit30=AGGREGATE, bit31=PREFIX. UNSIGNED (bit31 test must not sign-extend).
__device__ unsigned g_scan_state[NBLK];

#define FLAG_AGG    0x40000000u
#define FLAG_PREFIX 0x80000000u
#define VAL_MASK    0x3FFFFFFFu

// ---------------------------------------------------------------------------
// K1: zero deg + scan state
__global__ void k_zero() {
    int i = blockIdx.x * 1024 + threadIdx.x;
    if (i < N_NODES) g_deg[i] = 0;
    if (i < NBLK)    g_scan_state[i] = 0u;
}

// K2: degree count, 4 edges/thread
__global__ void k_deg(const int* __restrict__ dst) {
    int t = blockIdx.x * 256 + threadIdx.x;
    if (t >= N_EDGES / 4) return;
    int4 d4 = *reinterpret_cast<const int4*>(dst + t * 4);
    atomicAdd(&g_deg[d4.x], 1);
    atomicAdd(&g_deg[d4.y], 1);
    atomicAdd(&g_deg[d4.z], 1);
    atomicAdd(&g_deg[d4.w], 1);
}

// K3: single-pass decoupled-lookback exclusive scan of deg -> off, cursor; fused norm.
// 391 blocks fit in one wave -> lookback spin is residency-safe.
__global__ void k_scan() {
    __shared__ int s[256];
    __shared__ int s_base;
    int tid = threadIdx.x, bid = blockIdx.x;
    int i = bid * 256 + tid;
    int d = (i < N_NODES) ? g_deg[i] : 0;
    if (i < N_NODES) g_norm[i] = rsqrtf(fmaxf((float)d, 1.0f));

    s[tid] = d;
    __syncthreads();
#pragma unroll
    for (int off = 1; off < 256; off <<= 1) {
        int v = (tid >= off) ? s[tid - off] : 0;
        __syncthreads();
        s[tid] += v;
        __syncthreads();
    }
    int incl  = s[tid];
    int total = s[255];

    if (tid == 0) {
        if (bid == 0) {
            atomicExch(&g_scan_state[0], FLAG_PREFIX | (unsigned)total);
            s_base = 0;
        } else {
            atomicExch(&g_scan_state[bid], FLAG_AGG | (unsigned)total);
            int run = 0, j = bid - 1;
            while (true) {
                unsigned v;
                do { v = atomicAdd(&g_scan_state[j], 0u); }
                while ((v & (FLAG_AGG | FLAG_PREFIX)) == 0u);
                run += (int)(v & VAL_MASK);
                if (v & FLAG_PREFIX) break;
                j--;
            }
            atomicExch(&g_scan_state[bid], FLAG_PREFIX | (unsigned)(run + total));
            s_base = run;
        }
    }
    __syncthreads();
    if (i < N_NODES) {
        int excl = s_base + incl - d;
        g_off[i]    = excl;
        g_cursor[i] = excl;
    }
}

// K4: fill CSR (src ids grouped by dst)
__global__ void k_fill(const int* __restrict__ src, const int* __restrict__ dst) {
    int t = blockIdx.x * 256 + threadIdx.x;
    if (t >= N_EDGES / 4) return;
    int4 s4 = *reinterpret_cast<const int4*>(src + t * 4);
    int4 d4 = *reinterpret_cast<const int4*>(dst + t * 4);
    int p0 = atomicAdd(&g_cursor[d4.x], 1);
    int p1 = atomicAdd(&g_cursor[d4.y], 1);
    int p2 = atomicAdd(&g_cursor[d4.z], 1);
    int p3 = atomicAdd(&g_cursor[d4.w], 1);
    g_eidx[p0] = s4.x;
    g_eidx[p1] = s4.y;
    g_eidx[p2] = s4.z;
    g_eidx[p3] = s4.w;
}

// K5: gather-aggregate, 16 lanes/node, unroll-8 batched loads (MLP=8)
__global__ void __launch_bounds__(256)
k_gather(const float* __restrict__ feat) {
    int t = blockIdx.x * 256 + threadIdx.x;
    int n = t >> 4;
    int sub = t & 15;
    if (n >= N_NODES) return;
    int off = g_off[n];
    int deg = g_deg[n];
    float4 acc = make_float4(0.f, 0.f, 0.f, 0.f);
    int j = 0;
    for (; j + 8 <= deg; j += 8) {
        int   si[8];
        float nm[8];
        float4 f[8];
#pragma unroll
        for (int u = 0; u < 8; u++) si[u] = __ldg(&g_eidx[off + j + u]);
#pragma unroll
        for (int u = 0; u < 8; u++) nm[u] = __ldg(&g_norm[si[u]]);
#pragma unroll
        for (int u = 0; u < 8; u++)
            f[u] = *reinterpret_cast<const float4*>(feat + (size_t)si[u] * D + sub * 4);
#pragma unroll
        for (int u = 0; u < 8; u++) {
            acc.x = fmaf(f[u].x, nm[u], acc.x);
            acc.y = fmaf(f[u].y, nm[u], acc.y);
            acc.z = fmaf(f[u].z, nm[u], acc.z);
            acc.w = fmaf(f[u].w, nm[u], acc.w);
        }
    }
    for (; j + 4 <= deg; j += 4) {
        int   si[4];
        float nm[4];
        float4 f[4];
#pragma unroll
        for (int u = 0; u < 4; u++) si[u] = __ldg(&g_eidx[off + j + u]);
#pragma unroll
        for (int u = 0; u < 4; u++) nm[u] = __ldg(&g_norm[si[u]]);
#pragma unroll
        for (int u = 0; u < 4; u++)
            f[u] = *reinterpret_cast<const float4*>(feat + (size_t)si[u] * D + sub * 4);
#pragma unroll
        for (int u = 0; u < 4; u++) {
            acc.x = fmaf(f[u].x, nm[u], acc.x);
            acc.y = fmaf(f[u].y, nm[u], acc.y);
            acc.z = fmaf(f[u].z, nm[u], acc.z);
            acc.w = fmaf(f[u].w, nm[u], acc.w);
        }
    }
    for (; j < deg; j++) {
        int s0 = __ldg(&g_eidx[off + j]);
        float n0 = __ldg(&g_norm[s0]);
        float4 f0 = *reinterpret_cast<const float4*>(feat + (size_t)s0 * D + sub * 4);
        acc.x = fmaf(f0.x, n0, acc.x);
        acc.y = fmaf(f0.y, n0, acc.y);
        acc.z = fmaf(f0.z, n0, acc.z);
        acc.w = fmaf(f0.w, n0, acc.w);
    }
    float nd = g_norm[n];
    acc.x *= nd; acc.y *= nd; acc.z *= nd; acc.w *= nd;
    *reinterpret_cast<float4*>(g_agg + (size_t)n * D + sub * 4) = acc;
}

// ---------------------------------------------------------------------------
// K6: out = g_agg @ W^T + bias, packed f32x2 FMA
#define WT_PAD 68
#define A_PAD  65
#define SMEM_OUT_BYTES ((64 * WT_PAD + 256 * A_PAD) * 4)   // 83,968 B

__global__ void __launch_bounds__(256, 2)
k_out(const float* __restrict__ W,
      const float* __restrict__ bias,
      float* __restrict__ out) {
    extern __shared__ float sm[];
    float* w_sm = sm;                 // [64][WT_PAD]  w_sm[k][j] = W[j][k]
    float* a_sm = sm + 64 * WT_PAD;   // [256][A_PAD]
    int tid = threadIdx.x;

    for (int i = tid; i < 64 * 64; i += 256) {
        int j = i >> 6, k = i & 63;
        w_sm[k * WT_PAD + j] = W[i];
    }
    int nbase = blockIdx.x * 256;
#pragma unroll
    for (int it = 0; it < 16; it++) {
        int li = tid + it * 256;
        int nl = li >> 4, k4 = (li & 15) << 2;
        int n = nbase + nl;
        float4 v = make_float4(0.f, 0.f, 0.f, 0.f);
        if (n < N_NODES) v = *reinterpret_cast<const float4*>(g_agg + (size_t)n * D + k4);
        float* ap = a_sm + nl * A_PAD + k4;
        ap[0] = v.x; ap[1] = v.y; ap[2] = v.z; ap[3] = v.w;
    }
    __syncthreads();

    unsigned long long acc[32];
#pragma unroll
    for (int i = 0; i < 32; i++)
        acc[i] = __ldg(reinterpret_cast<const unsigned long long*>(bias) + i);

    const float* arow = a_sm + tid * A_PAD;
#pragma unroll 4
    for (int k = 0; k < 64; k++) {
        float ak = arow[k];
        unsigned long long ak2;
        asm("mov.b64 %0, {%1, %1};" : "=l"(ak2) : "r"(__float_as_uint(ak)));
        const unsigned long long* wrow =
            reinterpret_cast<const unsigned long long*>(w_sm + k * WT_PAD);
#pragma unroll
        for (int i = 0; i < 32; i++)
            asm("fma.rn.f32x2 %0, %1, %2, %0;" : "+l"(acc[i]) : "l"(ak2), "l"(wrow[i]));
    }

    int n = nbase + tid;
    if (n < N_NODES) {
        ulonglong2* o = reinterpret_cast<ulonglong2*>(out + (size_t)n * D);
#pragma unroll
        for (int i = 0; i < 16; i++) o[i] = make_ulonglong2(acc[2 * i], acc[2 * i + 1]);
    }
}

// ---------------------------------------------------------------------------
extern "C" void kernel_launch(void* const* d_in, const int* in_sizes, int n_in,
                              void* d_out, int out_size) {
    const float* feat = (const float*)d_in[0];
    const int*   src  = (const int*)d_in[1];
    const int*   dst  = (const int*)d_in[2];
    const float* W    = (const float*)d_in[3];
    const float* bias = (const float*)d_in[4];
    float* out = (float*)d_out;

    static bool attr_set = false;
    if (!attr_set) {
        cudaFuncSetAttribute(k_out, cudaFuncAttributeMaxDynamicSharedMemorySize,
                             SMEM_OUT_BYTES);
        attr_set = true;
    }

    k_zero<<<(N_NODES + 1023) / 1024, 1024>>>();
    k_deg<<<(N_EDGES / 4 + 255) / 256, 256>>>(dst);
    k_scan<<<NBLK, 256>>>();
    k_fill<<<(N_EDGES / 4 + 255) / 256, 256>>>(src, dst);
    k_gather<<<(N_NODES * 16 + 255) / 256, 256>>>(feat);
    k_out<<<NBLK, 256, SMEM_OUT_BYTES>>>(W, bias, out);
}